// round 1
// baseline (speedup 1.0000x reference)
#include <cuda_runtime.h>
#include <cuda_bf16.h>
#include <math.h>

// Problem dims (fixed by the reference)
#define DMODEL 1024
#define HEADS  16
#define DK     64
#define BATCH  8
#define SEQ    1024
#define MROWS  (BATCH * SEQ)   // 8192

// ---------------------------------------------------------------------------
// Scratch (no cudaMalloc allowed): Q, K, V projections + attention output
// ---------------------------------------------------------------------------
__device__ float g_Q[MROWS * DMODEL];
__device__ float g_K[MROWS * DMODEL];
__device__ float g_V[MROWS * DMODEL];
__device__ float g_AO[MROWS * DMODEL];

// ---------------------------------------------------------------------------
// SGEMM with bias: C[M,N] = A[M,K] @ W[K,N] + bias[N]
// BM=BN=128, BK=8, TM=TN=8, 256 threads. M,N,K all divisible by tile dims.
// ---------------------------------------------------------------------------
#define BM 128
#define BN 128
#define BK 8
#define TM 8
#define TN 8

__global__ __launch_bounds__(256, 2)
void sgemm_bias(const float* __restrict__ A, const float* __restrict__ W,
                const float* __restrict__ bias, float* __restrict__ C,
                int M, int N, int K)
{
    __shared__ float As[BK][BM];
    __shared__ float Bs[BK][BN];

    const int tid = threadIdx.x;
    const int brow = blockIdx.y;
    const int bcol = blockIdx.x;

    // output microtile coords
    const int trow = tid / (BN / TN);   // 0..15
    const int tcol = tid % (BN / TN);   // 0..15

    // A-tile load mapping: 128 rows x 8 k, one float4 per thread
    const int a_row  = tid >> 1;            // 0..127
    const int a_col4 = (tid & 1) * 4;       // 0 or 4
    // B-tile load mapping: 8 k-rows x 128 n, one float4 per thread
    const int b_row  = tid >> 5;            // 0..7
    const int b_col4 = (tid & 31) * 4;      // 0..124

    const float* Aptr = A + (size_t)(brow * BM) * K;
    const float* Wptr = W + (size_t)(bcol * BN);

    float acc[TM][TN];
    #pragma unroll
    for (int i = 0; i < TM; i++)
        #pragma unroll
        for (int j = 0; j < TN; j++)
            acc[i][j] = 0.0f;

    for (int k0 = 0; k0 < K; k0 += BK) {
        // load A tile (transposed into As[k][m])
        float4 a4 = *(const float4*)(Aptr + (size_t)a_row * K + k0 + a_col4);
        As[a_col4 + 0][a_row] = a4.x;
        As[a_col4 + 1][a_row] = a4.y;
        As[a_col4 + 2][a_row] = a4.z;
        As[a_col4 + 3][a_row] = a4.w;
        // load B tile
        float4 b4 = *(const float4*)(Wptr + (size_t)(k0 + b_row) * N + b_col4);
        *(float4*)&Bs[b_row][b_col4] = b4;
        __syncthreads();

        #pragma unroll
        for (int kk = 0; kk < BK; kk++) {
            float ra[TM], rb[TN];
            float4 t0 = *(const float4*)&As[kk][trow * TM];
            float4 t1 = *(const float4*)&As[kk][trow * TM + 4];
            ra[0]=t0.x; ra[1]=t0.y; ra[2]=t0.z; ra[3]=t0.w;
            ra[4]=t1.x; ra[5]=t1.y; ra[6]=t1.z; ra[7]=t1.w;
            float4 u0 = *(const float4*)&Bs[kk][tcol * TN];
            float4 u1 = *(const float4*)&Bs[kk][tcol * TN + 4];
            rb[0]=u0.x; rb[1]=u0.y; rb[2]=u0.z; rb[3]=u0.w;
            rb[4]=u1.x; rb[5]=u1.y; rb[6]=u1.z; rb[7]=u1.w;
            #pragma unroll
            for (int i = 0; i < TM; i++)
                #pragma unroll
                for (int j = 0; j < TN; j++)
                    acc[i][j] = fmaf(ra[i], rb[j], acc[i][j]);
        }
        __syncthreads();
    }

    // epilogue: add bias, vectorized stores
    const int crow = brow * BM + trow * TM;
    const int ccol = bcol * BN + tcol * TN;
    float4 bb0 = *(const float4*)(bias + ccol);
    float4 bb1 = *(const float4*)(bias + ccol + 4);
    #pragma unroll
    for (int i = 0; i < TM; i++) {
        float4 o0, o1;
        o0.x = acc[i][0] + bb0.x; o0.y = acc[i][1] + bb0.y;
        o0.z = acc[i][2] + bb0.z; o0.w = acc[i][3] + bb0.w;
        o1.x = acc[i][4] + bb1.x; o1.y = acc[i][5] + bb1.y;
        o1.z = acc[i][6] + bb1.z; o1.w = acc[i][7] + bb1.w;
        *(float4*)(C + (size_t)(crow + i) * N + ccol)     = o0;
        *(float4*)(C + (size_t)(crow + i) * N + ccol + 4) = o1;
    }
}

// ---------------------------------------------------------------------------
// Flash-style attention, fp32, online softmax.
// One q-row per thread (Q row + O accumulator live in registers).
// grid = (SEQ/QTILE, HEADS, BATCH), block = QTILE threads.
// K/V tiles of KTILE keys staged in smem; all inner-loop smem reads are
// warp-broadcast (every lane reads the same [j][d]) -> conflict-free.
// Softmax matches reference: mask==0 -> -1e20, scale = 1/sqrt(DMODEL).
// ---------------------------------------------------------------------------
#define QTILE 128
#define KTILE 64
#define CHUNK 16

__global__ __launch_bounds__(QTILE)
void flash_attn(const float* __restrict__ Q, const float* __restrict__ Km,
                const float* __restrict__ Vm, const int* __restrict__ mask,
                float* __restrict__ O)
{
    __shared__ float4 ks[KTILE * (DK / 4)];
    __shared__ float4 vs[KTILE * (DK / 4)];
    __shared__ int    ms[KTILE];

    const int qrow = blockIdx.x * QTILE + threadIdx.x;
    const int h    = blockIdx.y;
    const int b    = blockIdx.z;
    const float scale = 0.03125f;  // 1/sqrt(1024)

    // load my Q row into registers
    const float* qptr = Q + ((size_t)(b * SEQ + qrow)) * DMODEL + h * DK;
    float q[DK];
    #pragma unroll
    for (int d4 = 0; d4 < DK / 4; d4++) {
        float4 v = *(const float4*)(qptr + d4 * 4);
        q[d4*4+0] = v.x; q[d4*4+1] = v.y; q[d4*4+2] = v.z; q[d4*4+3] = v.w;
    }

    float o[DK];
    #pragma unroll
    for (int d = 0; d < DK; d++) o[d] = 0.0f;
    float m = -1e30f, l = 0.0f;

    for (int k0 = 0; k0 < SEQ; k0 += KTILE) {
        __syncthreads();   // previous tile fully consumed
        // stage K/V tile: KTILE*DK/4 = 1024 float4, 8 per thread
        for (int i = threadIdx.x; i < KTILE * (DK / 4); i += QTILE) {
            int j  = i / (DK / 4);
            int d4 = i % (DK / 4);
            size_t base = ((size_t)(b * SEQ + k0 + j)) * DMODEL + h * DK + d4 * 4;
            ks[i] = *(const float4*)(Km + base);
            vs[i] = *(const float4*)(Vm + base);
        }
        if (threadIdx.x < KTILE)
            ms[threadIdx.x] = mask[b * SEQ + k0 + threadIdx.x];
        __syncthreads();

        #pragma unroll 1
        for (int jc = 0; jc < KTILE; jc += CHUNK) {
            float s[CHUNK];
            float cm = -1e30f;
            #pragma unroll
            for (int jj = 0; jj < CHUNK; jj++) {
                const int j = jc + jj;
                float dot = 0.0f;
                #pragma unroll
                for (int d4 = 0; d4 < DK / 4; d4++) {
                    float4 k4 = ks[j * (DK / 4) + d4];
                    dot = fmaf(q[d4*4+0], k4.x, dot);
                    dot = fmaf(q[d4*4+1], k4.y, dot);
                    dot = fmaf(q[d4*4+2], k4.z, dot);
                    dot = fmaf(q[d4*4+3], k4.w, dot);
                }
                float sv = dot * scale;
                if (ms[j] == 0) sv = -1e20f;
                s[jj] = sv;
                cm = fmaxf(cm, sv);
            }
            const float mnew = fmaxf(m, cm);
            const float corr = __expf(m - mnew);
            m = mnew;
            l *= corr;
            #pragma unroll
            for (int d = 0; d < DK; d++) o[d] *= corr;
            #pragma unroll
            for (int jj = 0; jj < CHUNK; jj++) {
                const float p = __expf(s[jj] - mnew);
                l += p;
                const int j = jc + jj;
                #pragma unroll
                for (int d4 = 0; d4 < DK / 4; d4++) {
                    float4 v4 = vs[j * (DK / 4) + d4];
                    o[d4*4+0] = fmaf(p, v4.x, o[d4*4+0]);
                    o[d4*4+1] = fmaf(p, v4.y, o[d4*4+1]);
                    o[d4*4+2] = fmaf(p, v4.z, o[d4*4+2]);
                    o[d4*4+3] = fmaf(p, v4.w, o[d4*4+3]);
                }
            }
        }
    }

    const float inv = 1.0f / l;
    float* optr = O + ((size_t)(b * SEQ + qrow)) * DMODEL + h * DK;
    #pragma unroll
    for (int d4 = 0; d4 < DK / 4; d4++) {
        float4 v;
        v.x = o[d4*4+0] * inv; v.y = o[d4*4+1] * inv;
        v.z = o[d4*4+2] * inv; v.w = o[d4*4+3] * inv;
        *(float4*)(optr + d4 * 4) = v;
    }
}

// ---------------------------------------------------------------------------
// Launch: 3 projection GEMMs -> flash attention -> output GEMM
// Input order (metadata): values, keys, query, mask, Wq, bq, Wk, bk,
//                         Wv, bv, Wo, bo
// ---------------------------------------------------------------------------
extern "C" void kernel_launch(void* const* d_in, const int* in_sizes, int n_in,
                              void* d_out, int out_size)
{
    const float* values = (const float*)d_in[0];
    const float* keys   = (const float*)d_in[1];
    const float* query  = (const float*)d_in[2];
    const int*   mask   = (const int*)  d_in[3];
    const float* Wq = (const float*)d_in[4];
    const float* bq = (const float*)d_in[5];
    const float* Wk = (const float*)d_in[6];
    const float* bk = (const float*)d_in[7];
    const float* Wv = (const float*)d_in[8];
    const float* bv = (const float*)d_in[9];
    const float* Wo = (const float*)d_in[10];
    const float* bo = (const float*)d_in[11];
    float* out = (float*)d_out;

    float *dQ, *dK, *dV, *dAO;
    cudaGetSymbolAddress((void**)&dQ,  g_Q);
    cudaGetSymbolAddress((void**)&dK,  g_K);
    cudaGetSymbolAddress((void**)&dV,  g_V);
    cudaGetSymbolAddress((void**)&dAO, g_AO);

    dim3 gblk(256);
    dim3 ggrid(DMODEL / BN, MROWS / BM);   // (8, 64)

    // projections
    sgemm_bias<<<ggrid, gblk>>>(query,  Wq, bq, dQ, MROWS, DMODEL, DMODEL);
    sgemm_bias<<<ggrid, gblk>>>(keys,   Wk, bk, dK, MROWS, DMODEL, DMODEL);
    sgemm_bias<<<ggrid, gblk>>>(values, Wv, bv, dV, MROWS, DMODEL, DMODEL);

    // attention
    dim3 agrid(SEQ / QTILE, HEADS, BATCH); // (8, 16, 8)
    flash_attn<<<agrid, QTILE>>>(dQ, dK, dV, mask, dAO);

    // output projection
    sgemm_bias<<<ggrid, gblk>>>(dAO, Wo, bo, out, MROWS, DMODEL, DMODEL);
}

// round 4
// speedup vs baseline: 1.1191x; 1.1191x over previous
#include <cuda_runtime.h>
#include <cuda_bf16.h>
#include <cstdint>
#include <math.h>

// Problem dims
#define DMODEL 1024
#define HEADS  16
#define DK     64
#define BATCH  8
#define SEQ    1024
#define MROWS  (BATCH * SEQ)   // 8192

// Scratch
__device__ float g_Q[MROWS * DMODEL];
__device__ float g_K[MROWS * DMODEL];
__device__ float g_V[MROWS * DMODEL];
__device__ float g_AO[MROWS * DMODEL];

// ============================ helpers ============================
__device__ __forceinline__ uint32_t smem_u32(const void* p) {
    uint32_t a;
    asm("{ .reg .u64 t; cvta.to.shared.u64 t, %1; cvt.u32.u64 %0, t; }" : "=r"(a) : "l"(p));
    return a;
}
__device__ __forceinline__ void mma16816(float* d, const uint32_t* a, const uint32_t* b) {
    asm volatile(
        "mma.sync.aligned.m16n8k16.row.col.f32.bf16.bf16.f32 "
        "{%0,%1,%2,%3}, {%4,%5,%6,%7}, {%8,%9}, {%0,%1,%2,%3};"
        : "+f"(d[0]), "+f"(d[1]), "+f"(d[2]), "+f"(d[3])
        : "r"(a[0]), "r"(a[1]), "r"(a[2]), "r"(a[3]), "r"(b[0]), "r"(b[1]));
}
__device__ __forceinline__ void ldsm4(uint32_t* r, uint32_t addr) {
    asm volatile("ldmatrix.sync.aligned.m8n8.x4.shared.b16 {%0,%1,%2,%3}, [%4];"
        : "=r"(r[0]), "=r"(r[1]), "=r"(r[2]), "=r"(r[3]) : "r"(addr));
}
__device__ __forceinline__ void ldsm4t(uint32_t* r, uint32_t addr) {
    asm volatile("ldmatrix.sync.aligned.m8n8.x4.trans.shared.b16 {%0,%1,%2,%3}, [%4];"
        : "=r"(r[0]), "=r"(r[1]), "=r"(r[2]), "=r"(r[3]) : "r"(addr));
}
__device__ __forceinline__ uint32_t pack_bf2(float x, float y) {
    __nv_bfloat16 hx = __float2bfloat16(x);
    __nv_bfloat16 hy = __float2bfloat16(y);
    return (uint32_t)__bfloat16_as_ushort(hx) | ((uint32_t)__bfloat16_as_ushort(hy) << 16);
}
// split float4 -> hi (2x u32 of bf16x2) and lo residual
__device__ __forceinline__ void split4(float4 v, uint2& hi, uint2& lo) {
    __nv_bfloat16 hx = __float2bfloat16(v.x), hy = __float2bfloat16(v.y);
    __nv_bfloat16 hz = __float2bfloat16(v.z), hw = __float2bfloat16(v.w);
    hi.x = (uint32_t)__bfloat16_as_ushort(hx) | ((uint32_t)__bfloat16_as_ushort(hy) << 16);
    hi.y = (uint32_t)__bfloat16_as_ushort(hz) | ((uint32_t)__bfloat16_as_ushort(hw) << 16);
    lo.x = pack_bf2(v.x - __bfloat162float(hx), v.y - __bfloat162float(hy));
    lo.y = pack_bf2(v.z - __bfloat162float(hz), v.w - __bfloat162float(hw));
}

// ============================ HMMA GEMM ============================
// C[M,1024] = A[M,1024] @ W[1024,1024] + bias.  fp32 I/O, bf16x3 internal.
// CTA tile 128x128, BK=32, 256 threads = 8 warps (4m x 2n), warptile 32x64.
// A smem: [128 m][32 k] bf16, 64B rows, SW64 swizzle (chunk ^= (row>>1)&3).
// B smem: [32 k][128 n] bf16, 256B rows, swizzle (chunk ^= k&7).  (k-major, trans ldmatrix)
#define ABYTES 8192           // 128*64
#define BBYTES 8192           // 32*256
#define BUFBYTES (4 * 8192)   // Ahi Alo Bhi Blo
#define GEMM_SMEM (2 * BUFBYTES)   // 65536

__global__ __launch_bounds__(256, 1)
void gemm_hmma(const float* __restrict__ A, const float* __restrict__ W,
               const float* __restrict__ bias, float* __restrict__ C)
{
    extern __shared__ char sm[];
    const uint32_t smb = smem_u32(sm);
    const int tid  = threadIdx.x;
    const int wid  = tid >> 5;
    const int lane = tid & 31;
    const int m0 = blockIdx.y * 128;
    const int n0 = blockIdx.x * 128;

    const int warp_m = wid & 3;   // 0..3 -> m offset *32
    const int warp_n = wid >> 2;  // 0..1 -> n offset *64

    // ---- staging coords ----
    const int aRow = tid >> 3;          // + 32*j
    const int aC4  = tid & 7;
    const int bK   = tid >> 5;          // + 8*j
    const int bN4  = tid & 31;

    // precomputed swizzled STS offsets (within a buffer's A/B region)
    uint32_t aStsOff[4], bStsOff[4];
    #pragma unroll
    for (int j = 0; j < 4; j++) {
        int row = aRow + 32 * j;
        uint32_t o = row * 64 + aC4 * 8;
        aStsOff[j] = o ^ (((row >> 1) & 3) << 4);
        int k = bK + 8 * j;
        bStsOff[j] = k * 256 + (((bN4 >> 1) ^ (k & 7)) << 4) + (bN4 & 1) * 8;
    }

    // ---- ldmatrix lane addressing ----
    const int grp  = lane >> 3;      // 0..3
    const int lrow = lane & 7;
    // A: rows within 16-row tile
    const int aFr  = ((grp & 1) << 3) + lrow;        // 0..15
    const int aCs  = grp >> 1;                       // chunk within pair
    // B: k within 16, chunk offset
    const int bFk  = ((grp & 1) << 3) + lrow;        // 0..15
    const int bCs  = grp >> 1;

    float acc[2][8][4];
    #pragma unroll
    for (int i = 0; i < 2; i++)
        #pragma unroll
        for (int j = 0; j < 8; j++)
            #pragma unroll
            for (int c = 0; c < 4; c++) acc[i][j][c] = 0.0f;

    const float* Ab = A + (size_t)m0 * DMODEL;
    float4 aF[4], bF[4];

    // prologue: load + stage s=0
    #pragma unroll
    for (int j = 0; j < 4; j++) {
        aF[j] = *(const float4*)(Ab + (size_t)(aRow + 32 * j) * DMODEL + aC4 * 4);
        bF[j] = *(const float4*)(W + (size_t)(bK + 8 * j) * DMODEL + n0 + bN4 * 4);
    }
    {
        char* buf = sm;
        #pragma unroll
        for (int j = 0; j < 4; j++) {
            uint2 hi, lo;
            split4(aF[j], hi, lo);
            *(uint2*)(buf + aStsOff[j])         = hi;
            *(uint2*)(buf + ABYTES + aStsOff[j]) = lo;
            split4(bF[j], hi, lo);
            *(uint2*)(buf + 2 * ABYTES + bStsOff[j]) = hi;
            *(uint2*)(buf + 3 * ABYTES + bStsOff[j]) = lo;
        }
    }
    __syncthreads();

    for (int s = 0; s < 32; s++) {
        // prefetch next stage fp32 into regs
        if (s + 1 < 32) {
            const int k0 = (s + 1) * 32;
            #pragma unroll
            for (int j = 0; j < 4; j++) {
                aF[j] = *(const float4*)(Ab + (size_t)(aRow + 32 * j) * DMODEL + k0 + aC4 * 4);
                bF[j] = *(const float4*)(W + (size_t)(k0 + bK + 8 * j) * DMODEL + n0 + bN4 * 4);
            }
        }
        // ---- MMA on buffer s&1 ----
        {
            const uint32_t bufb = smb + (s & 1) * BUFBYTES;
            const uint32_t Ahi = bufb, Alo = bufb + ABYTES;
            const uint32_t Bhi = bufb + 2 * ABYTES, Blo = bufb + 3 * ABYTES;
            #pragma unroll
            for (int kp = 0; kp < 2; kp++) {
                uint32_t ahi[2][4], alo[2][4];
                #pragma unroll
                for (int mt = 0; mt < 2; mt++) {
                    int row = warp_m * 32 + mt * 16 + aFr;
                    int chunk = 2 * kp + aCs;
                    uint32_t co = (uint32_t)(chunk ^ ((row >> 1) & 3)) << 4;
                    ldsm4(ahi[mt], Ahi + row * 64 + co);
                    ldsm4(alo[mt], Alo + row * 64 + co);
                }
                uint32_t bhi[8][2], blo[8][2];
                #pragma unroll
                for (int np = 0; np < 4; np++) {
                    int k = kp * 16 + bFk;
                    int chunk = warp_n * 8 + np * 2 + bCs;
                    uint32_t addr = k * 256 + ((uint32_t)(chunk ^ (k & 7)) << 4);
                    uint32_t t[4];
                    ldsm4t(t, Bhi + addr);
                    bhi[2*np][0] = t[0]; bhi[2*np][1] = t[1];
                    bhi[2*np+1][0] = t[2]; bhi[2*np+1][1] = t[3];
                    ldsm4t(t, Blo + addr);
                    blo[2*np][0] = t[0]; blo[2*np][1] = t[1];
                    blo[2*np+1][0] = t[2]; blo[2*np+1][1] = t[3];
                }
                #pragma unroll
                for (int mt = 0; mt < 2; mt++)
                    #pragma unroll
                    for (int nt = 0; nt < 8; nt++) {
                        mma16816(acc[mt][nt], ahi[mt], bhi[nt]);
                        mma16816(acc[mt][nt], ahi[mt], blo[nt]);
                        mma16816(acc[mt][nt], alo[mt], bhi[nt]);
                    }
            }
        }
        // ---- stage s+1 into other buffer ----
        if (s + 1 < 32) {
            char* buf = sm + ((s + 1) & 1) * BUFBYTES;
            #pragma unroll
            for (int j = 0; j < 4; j++) {
                uint2 hi, lo;
                split4(aF[j], hi, lo);
                *(uint2*)(buf + aStsOff[j])          = hi;
                *(uint2*)(buf + ABYTES + aStsOff[j]) = lo;
                split4(bF[j], hi, lo);
                *(uint2*)(buf + 2 * ABYTES + bStsOff[j]) = hi;
                *(uint2*)(buf + 3 * ABYTES + bStsOff[j]) = lo;
            }
            __syncthreads();
        }
    }

    // ---- epilogue ----
    const int rbase = m0 + warp_m * 32 + (lane >> 2);
    const int cbase = n0 + warp_n * 64 + (lane & 3) * 2;
    #pragma unroll
    for (int mt = 0; mt < 2; mt++) {
        #pragma unroll
        for (int nt = 0; nt < 8; nt++) {
            int col = cbase + nt * 8;
            float b0 = bias[col], b1 = bias[col + 1];
            int r0 = rbase + mt * 16;
            float2 v0 = make_float2(acc[mt][nt][0] + b0, acc[mt][nt][1] + b1);
            float2 v1 = make_float2(acc[mt][nt][2] + b0, acc[mt][nt][3] + b1);
            *(float2*)(C + (size_t)r0 * DMODEL + col)       = v0;
            *(float2*)(C + (size_t)(r0 + 8) * DMODEL + col) = v1;
        }
    }
}

// ============================ Flash attention (fp32, 2 threads/row) ============================
#define QTILE 128
#define KTILE 64
#define CHUNK 16

__global__ __launch_bounds__(256, 2)
void flash_attn(const float* __restrict__ Q, const float* __restrict__ Km,
                const float* __restrict__ Vm, const int* __restrict__ mask,
                float* __restrict__ O)
{
    __shared__ float4 ks[KTILE * (DK / 4)];
    __shared__ float4 vs[KTILE * (DK / 4)];
    __shared__ int    ms[KTILE];

    const int tid  = threadIdx.x;
    const int qrow = blockIdx.x * QTILE + (tid >> 1);
    const int half = tid & 1;           // which 32 dims this thread owns
    const int h    = blockIdx.y;
    const int b    = blockIdx.z;
    const float scale = 0.03125f;  // 1/sqrt(1024)
    const int h8 = half * 8;       // float4 offset of my half

    const float* qptr = Q + ((size_t)(b * SEQ + qrow)) * DMODEL + h * DK + half * 32;
    float q[32];
    #pragma unroll
    for (int d4 = 0; d4 < 8; d4++) {
        float4 v = *(const float4*)(qptr + d4 * 4);
        q[d4*4+0] = v.x; q[d4*4+1] = v.y; q[d4*4+2] = v.z; q[d4*4+3] = v.w;
    }

    float o[32];
    #pragma unroll
    for (int d = 0; d < 32; d++) o[d] = 0.0f;
    float m = -1e30f, l = 0.0f;

    for (int k0 = 0; k0 < SEQ; k0 += KTILE) {
        __syncthreads();
        for (int i = tid; i < KTILE * (DK / 4); i += 256) {
            int j  = i / (DK / 4);
            int d4 = i % (DK / 4);
            size_t base = ((size_t)(b * SEQ + k0 + j)) * DMODEL + h * DK + d4 * 4;
            ks[i] = *(const float4*)(Km + base);
            vs[i] = *(const float4*)(Vm + base);
        }
        if (tid < KTILE)
            ms[tid] = mask[b * SEQ + k0 + tid];
        __syncthreads();

        #pragma unroll 1
        for (int jc = 0; jc < KTILE; jc += CHUNK) {
            float s[CHUNK];
            float cm = -1e30f;
            #pragma unroll
            for (int jj = 0; jj < CHUNK; jj++) {
                const int j = jc + jj;
                float dot = 0.0f;
                #pragma unroll
                for (int d4 = 0; d4 < 8; d4++) {
                    float4 k4 = ks[j * (DK / 4) + h8 + d4];
                    dot = fmaf(q[d4*4+0], k4.x, dot);
                    dot = fmaf(q[d4*4+1], k4.y, dot);
                    dot = fmaf(q[d4*4+2], k4.z, dot);
                    dot = fmaf(q[d4*4+3], k4.w, dot);
                }
                dot += __shfl_xor_sync(0xffffffffu, dot, 1);
                float sv = dot * scale;
                if (ms[j] == 0) sv = -1e20f;
                s[jj] = sv;
                cm = fmaxf(cm, sv);
            }
            const float mnew = fmaxf(m, cm);
            const float corr = __expf(m - mnew);
            m = mnew;
            l *= corr;
            #pragma unroll
            for (int d = 0; d < 32; d++) o[d] *= corr;
            #pragma unroll
            for (int jj = 0; jj < CHUNK; jj++) {
                const float p = __expf(s[jj] - mnew);
                l += p;
                const int j = jc + jj;
                #pragma unroll
                for (int d4 = 0; d4 < 8; d4++) {
                    float4 v4 = vs[j * (DK / 4) + h8 + d4];
                    o[d4*4+0] = fmaf(p, v4.x, o[d4*4+0]);
                    o[d4*4+1] = fmaf(p, v4.y, o[d4*4+1]);
                    o[d4*4+2] = fmaf(p, v4.z, o[d4*4+2]);
                    o[d4*4+3] = fmaf(p, v4.w, o[d4*4+3]);
                }
            }
        }
    }

    const float inv = 1.0f / l;
    float* optr = O + ((size_t)(b * SEQ + qrow)) * DMODEL + h * DK + half * 32;
    #pragma unroll
    for (int d4 = 0; d4 < 8; d4++) {
        float4 v;
        v.x = o[d4*4+0] * inv; v.y = o[d4*4+1] * inv;
        v.z = o[d4*4+2] * inv; v.w = o[d4*4+3] * inv;
        *(float4*)(optr + d4 * 4) = v;
    }
}

// ============================ Launch ============================
extern "C" void kernel_launch(void* const* d_in, const int* in_sizes, int n_in,
                              void* d_out, int out_size)
{
    const float* values = (const float*)d_in[0];
    const float* keys   = (const float*)d_in[1];
    const float* query  = (const float*)d_in[2];
    const int*   mask   = (const int*)  d_in[3];
    const float* Wq = (const float*)d_in[4];
    const float* bq = (const float*)d_in[5];
    const float* Wk = (const float*)d_in[6];
    const float* bk = (const float*)d_in[7];
    const float* Wv = (const float*)d_in[8];
    const float* bv = (const float*)d_in[9];
    const float* Wo = (const float*)d_in[10];
    const float* bo = (const float*)d_in[11];
    float* out = (float*)d_out;

    float *dQ, *dK, *dV, *dAO;
    cudaGetSymbolAddress((void**)&dQ,  g_Q);
    cudaGetSymbolAddress((void**)&dK,  g_K);
    cudaGetSymbolAddress((void**)&dV,  g_V);
    cudaGetSymbolAddress((void**)&dAO, g_AO);

    // idempotent; safe to call every time (not a stream op)
    cudaFuncSetAttribute(gemm_hmma, cudaFuncAttributeMaxDynamicSharedMemorySize, GEMM_SMEM);

    dim3 gblk(256);
    dim3 ggrid(DMODEL / 128, MROWS / 128);   // (8, 64)

    gemm_hmma<<<ggrid, gblk, GEMM_SMEM>>>(query,  Wq, bq, dQ);
    gemm_hmma<<<ggrid, gblk, GEMM_SMEM>>>(keys,   Wk, bk, dK);
    gemm_hmma<<<ggrid, gblk, GEMM_SMEM>>>(values, Wv, bv, dV);

    dim3 agrid(SEQ / QTILE, HEADS, BATCH);   // (8, 16, 8)
    flash_attn<<<agrid, 256>>>(dQ, dK, dV, mask, dAO);

    gemm_hmma<<<ggrid, gblk, GEMM_SMEM>>>(dAO, Wo, bo, out);
}